// round 11
// baseline (speedup 1.0000x reference)
#include <cuda_runtime.h>
#include <cuda_fp16.h>
#include <cstdint>

// ============ problem constants ============
#define M_FIXED 512
#define K_FIXED 8192
#define N_FIXED 8192
#define NPACK   (N_FIXED / 2)

#define BM 256
#define BN 128
#define BK 64
#define NSTAGE 3
#define NTHREADS 640   // 16 consumer warps (4m x 4n, 64x32) + 4 producer warps
#define NK (K_FIXED / BK)

// Precomputed A = x*su in fp16, row-major [M][K]
__device__ __half g_A[M_FIXED * (size_t)K_FIXED];

// ============ smem layout (bytes) ============
#define SM_TAB  0                     // half2 LUT, 4 copies x 256 x 4B = 4096
#define SM_MBAR 4096                  // full[3]/empty[3]: 6 x 8B
#define SM_A    8192                  // 3 stages x 256 rows x 128 B
#define SM_B    (SM_A + NSTAGE * 32768)
#define SMEM_TOTAL (SM_B + NSTAGE * 16384)   // 155648 B

#define SW128(off) ((off) ^ (((off) >> 3) & 0x70))

__device__ __forceinline__ uint32_t smem_u32(const void* p) {
    uint32_t a;
    asm("{ .reg .u64 t; cvta.to.shared.u64 t, %1; cvt.u32.u64 %0, t; }" : "=r"(a) : "l"(p));
    return a;
}
__device__ __forceinline__ void cp_async16(uint32_t dst, const void* src) {
    asm volatile("cp.async.cg.shared.global [%0], [%1], 16;" :: "r"(dst), "l"(src));
}
__device__ __forceinline__ void ldsm4(uint32_t& r0, uint32_t& r1, uint32_t& r2,
                                      uint32_t& r3, uint32_t addr) {
    asm volatile("ldmatrix.sync.aligned.m8n8.x4.shared.b16 {%0,%1,%2,%3}, [%4];"
                 : "=r"(r0), "=r"(r1), "=r"(r2), "=r"(r3) : "r"(addr));
}
__device__ __forceinline__ void mma16816(float* d, const uint32_t* a, const uint32_t* b) {
    asm volatile(
        "mma.sync.aligned.m16n8k16.row.col.f32.f16.f16.f32 "
        "{%0,%1,%2,%3}, {%4,%5,%6,%7}, {%8,%9}, {%0,%1,%2,%3};"
        : "+f"(d[0]), "+f"(d[1]), "+f"(d[2]), "+f"(d[3])
        : "r"(a[0]), "r"(a[1]), "r"(a[2]), "r"(a[3]), "r"(b[0]), "r"(b[1]));
}
__device__ __forceinline__ uint32_t h2pack(float lo, float hi) {
    __half2 v = __floats2half2_rn(lo, hi);
    return *reinterpret_cast<uint32_t*>(&v);
}
__device__ __forceinline__ uint32_t hmul2(uint32_t a, uint32_t b) {
    uint32_t r;
    asm("mul.f16x2 %0, %1, %2;" : "=r"(r) : "r"(a), "r"(b));
    return r;
}

#define MBAR_INIT(addr, cnt) \
    asm volatile("mbarrier.init.shared.b64 [%0], %1;" :: "r"(addr), "r"(cnt) : "memory")
#define MBAR_ARRIVE(addr) \
    asm volatile("mbarrier.arrive.shared.b64 _, [%0];" :: "r"(addr) : "memory")
#define CP_ASYNC_MBAR_ARRIVE(addr) \
    asm volatile("cp.async.mbarrier.arrive.shared.b64 [%0];" :: "r"(addr) : "memory")
#define MBAR_WAIT(addr, par) do {                                              \
    uint32_t _m = (addr), _p = (par), _d;                                      \
    asm volatile("{ .reg .pred p; mbarrier.try_wait.parity.acquire.cta.shared::cta.b64 p, [%1], %2;" \
                 " selp.b32 %0, 1, 0, p; }" : "=r"(_d) : "r"(_m), "r"(_p) : "memory"); \
    if (!_d) {                                                                 \
        asm volatile("{ .reg .pred P1; WL_%=:"                                 \
            " mbarrier.try_wait.parity.acquire.cta.shared::cta.b64 P1, [%0], %1, 0x989680;" \
            " @P1 bra.uni WD_%=; bra.uni WL_%=; WD_%=: }"                      \
            :: "r"(_m), "r"(_p) : "memory");                                   \
    } } while (0)

// ============ kernel 1: A = x * su -> fp16 ============
__global__ __launch_bounds__(256) void precompute_a(const float* __restrict__ x,
                                                    const float* __restrict__ su) {
    int i4 = blockIdx.x * 256 + threadIdx.x;
    size_t base = (size_t)i4 * 4;
    int k = (int)(base & (K_FIXED - 1));
    float4 xv = *reinterpret_cast<const float4*>(x + base);
    float4 s  = *reinterpret_cast<const float4*>(su + k);
    uint2 o;
    o.x = h2pack(xv.x * s.x, xv.y * s.y);
    o.y = h2pack(xv.z * s.z, xv.w * s.w);
    *reinterpret_cast<uint2*>(reinterpret_cast<char*>(g_A) + base * 2) = o;
}

// ============ kernel 2: warp-specialized fp16 HMMA GEMM ============
__global__ __launch_bounds__(NTHREADS, 1) void trellis_mma_kernel(
    const int*   __restrict__ packed,
    const float* __restrict__ grid,
    const float* __restrict__ scales,
    const float* __restrict__ sv,
    float*       __restrict__ out)
{
    extern __shared__ char smem[];
    const uint32_t sbase = smem_u32(smem);
    uint32_t* tab = reinterpret_cast<uint32_t*>(smem + SM_TAB);

    const int tid = threadIdx.x;
    const int lid = tid & 31;
    const int wid = tid >> 5;
    const int mbase = blockIdx.x * BM;
    const int nbase = blockIdx.y * BN;

    const uint32_t mb = sbase + SM_MBAR;  // full[s] at +s*16, empty[s] at +s*16+8

    for (int e = tid; e < 1024; e += NTHREADS) {
        int b = e & 255;
        tab[e] = h2pack(grid[b & 15], grid[(b >> 4) & 15]);
    }
    if (tid == 0) {
        #pragma unroll
        for (int s = 0; s < NSTAGE; s++) {
            // full: 128 explicit producer arrives (cp.async.mbarrier.arrive is
            // count-neutral and only delays the phase until A copies land).
            MBAR_INIT(mb + s * 16, 128);
            MBAR_INIT(mb + s * 16 + 8, 512);  // empty: 512 consumer threads
        }
    }
    __syncthreads();

    if (wid >= 16) {
        // ====== PRODUCER: 4 warps, 128 threads = (64 n-pairs) x (2 k-halves)
        const int ptid = tid - 512;          // 0..127
        const int np = ptid & 63;            // n-pair
        const int kh = ptid >> 6;            // k-half: 0 -> k[0,32), 1 -> k[32,64)
        const int n0 = 2 * np;
        const int* pcol = packed + (size_t)(kh * 32) * NPACK + (nbase >> 1) + np;
        const float* scp0 = scales + nbase + n0;
        const float sv0 = sv[nbase + n0], sv1 = sv[nbase + n0 + 1];
        const uint32_t* tabc = tab + ((ptid >> 3) & 3) * 256;

        for (int i = 0; i < NK; i++) {
            const int s = i % NSTAGE;
            const int w = i / NSTAGE;
            const uint32_t fullb  = mb + s * 16;
            const uint32_t emptyb = mb + s * 16 + 8;
            if (w) MBAR_WAIT(emptyb, (uint32_t)((w - 1) & 1));
            const int k0 = i * BK;

            // ---- A: 2048 chunks / 128 thr = 16 cp.async each ----
            #pragma unroll
            for (int c = 0; c < 16; c++) {
                int q = ptid + c * 128;      // 0..2047
                int row = q >> 3;
                int cc = q & 7;
                cp_async16(sbase + SM_A + s * 32768 +
                               SW128((uint32_t)(row * 128 + cc * 16)),
                           g_A + (size_t)(mbase + row) * K_FIXED + k0 + cc * 8);
            }
            CP_ASYNC_MBAR_ARRIVE(fullb);

            // ---- B: 32 packed LDG + dequant + 8 STS.128 (this thread's k-half)
            const int g = k0 >> 7;
            __half2 t0 = __float2half2_rn(scp0[(size_t)g * N_FIXED]     * sv0);
            __half2 t1 = __float2half2_rn(scp0[(size_t)g * N_FIXED + 1] * sv1);
            const uint32_t hsc0 = *reinterpret_cast<uint32_t*>(&t0);
            const uint32_t hsc1 = *reinterpret_cast<uint32_t*>(&t1);
            const int* prow = pcol + (size_t)k0 * NPACK;
            char* bstage = smem + SM_B + s * 16384;

            #pragma unroll
            for (int sub = 0; sub < 2; sub++) {      // two 16-k chunks
                int pb[16];
                #pragma unroll
                for (int j = 0; j < 16; j++)
                    pb[j] = prow[(size_t)(sub * 16 + j) * NPACK];
                uint32_t o0[8], o1[8];
                #pragma unroll
                for (int j = 0; j < 8; j++) {
                    uint32_t wa = tabc[pb[2 * j] & 255];
                    uint32_t wb = tabc[pb[2 * j + 1] & 255];
                    uint32_t u0 = __byte_perm(wa, wb, 0x5410);
                    uint32_t u1 = __byte_perm(wa, wb, 0x7632);
                    o0[j] = hmul2(u0, hsc0);
                    o1[j] = hmul2(u1, hsc1);
                }
                uint32_t b0 = (uint32_t)(n0 * 128 + kh * 64 + sub * 32);
                uint32_t b1 = (uint32_t)((n0 + 1) * 128 + kh * 64 + sub * 32);
                *reinterpret_cast<uint4*>(bstage + SW128(b0))      = make_uint4(o0[0], o0[1], o0[2], o0[3]);
                *reinterpret_cast<uint4*>(bstage + SW128(b0 + 16)) = make_uint4(o0[4], o0[5], o0[6], o0[7]);
                *reinterpret_cast<uint4*>(bstage + SW128(b1))      = make_uint4(o1[0], o1[1], o1[2], o1[3]);
                *reinterpret_cast<uint4*>(bstage + SW128(b1 + 16)) = make_uint4(o1[4], o1[5], o1[6], o1[7]);
            }
            MBAR_ARRIVE(fullb);
        }
    } else {
        // ============ CONSUMER: 16 warps, 4m x 4n, warp tile 64x32 =========
        const int mw = wid >> 2;        // 0..3 -> m offset 64*mw
        const int nw = wid & 3;         // 0..3 -> n offset 32*nw
        const int arow = (lid & 15);
        const int khalf = (lid >> 4) * 16;

        float acc[4][4][4];
        #pragma unroll
        for (int mi = 0; mi < 4; mi++)
            #pragma unroll
            for (int ni = 0; ni < 4; ni++)
                #pragma unroll
                for (int v = 0; v < 4; v++) acc[mi][ni][v] = 0.f;

        for (int i = 0; i < NK; i++) {
            const int s = i % NSTAGE;
            const int w = i / NSTAGE;
            MBAR_WAIT(mb + s * 16, (uint32_t)(w & 1));
            const uint32_t abase = sbase + SM_A + s * 32768;
            const uint32_t bbase = sbase + SM_B + s * 16384;

            #pragma unroll
            for (int kk = 0; kk < 4; kk++) {
                const uint32_t kb = (uint32_t)(kk * 32 + khalf);
                uint32_t bf[4][2];
                #pragma unroll
                for (int nj = 0; nj < 2; nj++) {
                    uint32_t ro = (uint32_t)((nw * 32 + nj * 16 + arow) * 128);
                    uint32_t r0, r1, r2, r3;
                    ldsm4(r0, r1, r2, r3, bbase + SW128(ro + kb));
                    bf[2 * nj][0] = r0; bf[2 * nj][1] = r2;
                    bf[2 * nj + 1][0] = r1; bf[2 * nj + 1][1] = r3;
                }
                #pragma unroll
                for (int mi = 0; mi < 4; mi++) {
                    uint32_t ah[4];
                    uint32_t ro = (uint32_t)((mw * 64 + mi * 16 + arow) * 128);
                    ldsm4(ah[0], ah[1], ah[2], ah[3], abase + SW128(ro + kb));
                    #pragma unroll
                    for (int ni = 0; ni < 4; ni++)
                        mma16816(acc[mi][ni], ah, bf[ni]);
                }
            }
            MBAR_ARRIVE(mb + s * 16 + 8);
        }

        // ---- epilogue ----
        const int er = lid >> 2;
        const int ec = (lid & 3) * 2;
        #pragma unroll
        for (int mi = 0; mi < 4; mi++) {
            #pragma unroll
            for (int ni = 0; ni < 4; ni++) {
                int row = mbase + mw * 64 + mi * 16 + er;
                int col = nbase + nw * 32 + ni * 8 + ec;
                *reinterpret_cast<float2*>(out + (size_t)row * N_FIXED + col) =
                    make_float2(acc[mi][ni][0], acc[mi][ni][1]);
                *reinterpret_cast<float2*>(out + (size_t)(row + 8) * N_FIXED + col) =
                    make_float2(acc[mi][ni][2], acc[mi][ni][3]);
            }
        }
    }
}

// ============ host launcher ============
extern "C" void kernel_launch(void* const* d_in, const int* in_sizes, int n_in,
                              void* d_out, int out_size)
{
    const float* x      = (const float*)d_in[0];
    const int*   packed = (const int*)  d_in[1];
    const float* grid   = (const float*)d_in[2];
    const float* scales = (const float*)d_in[3];
    const float* su     = (const float*)d_in[4];
    const float* sv     = (const float*)d_in[5];
    float* out = (float*)d_out;

    cudaFuncSetAttribute(trellis_mma_kernel,
                         cudaFuncAttributeMaxDynamicSharedMemorySize, SMEM_TOTAL);

    precompute_a<<<(M_FIXED * K_FIXED) / 1024, 256>>>(x, su);

    dim3 grd(M_FIXED / BM, N_FIXED / BN);
    trellis_mma_kernel<<<grd, NTHREADS, SMEM_TOTAL>>>(packed, grid, scales, sv, out);
}

// round 12
// speedup vs baseline: 1.0428x; 1.0428x over previous
#include <cuda_runtime.h>
#include <cuda_fp16.h>
#include <cstdint>

// ============ problem constants ============
#define M_FIXED 512
#define K_FIXED 8192
#define N_FIXED 8192
#define NPACK   (N_FIXED / 2)

#define BM 256
#define BN 128
#define BK 64
#define SPLITK 8
#define KCHUNK (K_FIXED / SPLITK)     // 1024
#define NK_LOCAL (KCHUNK / BK)        // 16
#define NSTAGE 3
#define NTHREADS 384   // 8 consumer warps (4m x 2n, 64x64) + 4 producer warps

// Precomputed A = x*su in fp16, row-major [M][K]
__device__ __half g_A[M_FIXED * (size_t)K_FIXED];

// ============ smem layout (bytes) ============
#define SM_TAB  0                     // half2 LUT, 4 copies x 256 x 4B = 4096
#define SM_MBAR 4096                  // full[3]/empty[3]: 6 x 8B
#define SM_A    8192                  // 3 stages x 256 rows x 128 B
#define SM_B    (SM_A + NSTAGE * 32768)
#define SMEM_TOTAL (SM_B + NSTAGE * 16384)   // 155648 B

#define SW128(off) ((off) ^ (((off) >> 3) & 0x70))

__device__ __forceinline__ uint32_t smem_u32(const void* p) {
    uint32_t a;
    asm("{ .reg .u64 t; cvta.to.shared.u64 t, %1; cvt.u32.u64 %0, t; }" : "=r"(a) : "l"(p));
    return a;
}
__device__ __forceinline__ void cp_async16(uint32_t dst, const void* src) {
    asm volatile("cp.async.cg.shared.global [%0], [%1], 16;" :: "r"(dst), "l"(src));
}
__device__ __forceinline__ void ldsm4(uint32_t& r0, uint32_t& r1, uint32_t& r2,
                                      uint32_t& r3, uint32_t addr) {
    asm volatile("ldmatrix.sync.aligned.m8n8.x4.shared.b16 {%0,%1,%2,%3}, [%4];"
                 : "=r"(r0), "=r"(r1), "=r"(r2), "=r"(r3) : "r"(addr));
}
__device__ __forceinline__ void mma16816(float* d, const uint32_t* a, const uint32_t* b) {
    asm volatile(
        "mma.sync.aligned.m16n8k16.row.col.f32.f16.f16.f32 "
        "{%0,%1,%2,%3}, {%4,%5,%6,%7}, {%8,%9}, {%0,%1,%2,%3};"
        : "+f"(d[0]), "+f"(d[1]), "+f"(d[2]), "+f"(d[3])
        : "r"(a[0]), "r"(a[1]), "r"(a[2]), "r"(a[3]), "r"(b[0]), "r"(b[1]));
}
__device__ __forceinline__ uint32_t h2pack(float lo, float hi) {
    __half2 v = __floats2half2_rn(lo, hi);
    return *reinterpret_cast<uint32_t*>(&v);
}
__device__ __forceinline__ uint32_t hmul2(uint32_t a, uint32_t b) {
    uint32_t r;
    asm("mul.f16x2 %0, %1, %2;" : "=r"(r) : "r"(a), "r"(b));
    return r;
}
__device__ __forceinline__ void redadd(float* p, float v) {
    asm volatile("red.global.add.f32 [%0], %1;" :: "l"(p), "f"(v) : "memory");
}

#define MBAR_INIT(addr, cnt) \
    asm volatile("mbarrier.init.shared.b64 [%0], %1;" :: "r"(addr), "r"(cnt) : "memory")
#define MBAR_ARRIVE(addr) \
    asm volatile("mbarrier.arrive.shared.b64 _, [%0];" :: "r"(addr) : "memory")
#define CP_ASYNC_MBAR_ARRIVE(addr) \
    asm volatile("cp.async.mbarrier.arrive.shared.b64 [%0];" :: "r"(addr) : "memory")
#define MBAR_WAIT(addr, par) do {                                              \
    uint32_t _m = (addr), _p = (par), _d;                                      \
    asm volatile("{ .reg .pred p; mbarrier.try_wait.parity.acquire.cta.shared::cta.b64 p, [%1], %2;" \
                 " selp.b32 %0, 1, 0, p; }" : "=r"(_d) : "r"(_m), "r"(_p) : "memory"); \
    if (!_d) {                                                                 \
        asm volatile("{ .reg .pred P1; WL_%=:"                                 \
            " mbarrier.try_wait.parity.acquire.cta.shared::cta.b64 P1, [%0], %1, 0x989680;" \
            " @P1 bra.uni WD_%=; bra.uni WL_%=; WD_%=: }"                      \
            :: "r"(_m), "r"(_p) : "memory");                                   \
    } } while (0)

// ============ kernel 1: A = x * su -> fp16 ============
__global__ __launch_bounds__(256) void precompute_a(const float* __restrict__ x,
                                                    const float* __restrict__ su) {
    int i4 = blockIdx.x * 256 + threadIdx.x;
    size_t base = (size_t)i4 * 4;
    int k = (int)(base & (K_FIXED - 1));
    float4 xv = *reinterpret_cast<const float4*>(x + base);
    float4 s  = *reinterpret_cast<const float4*>(su + k);
    uint2 o;
    o.x = h2pack(xv.x * s.x, xv.y * s.y);
    o.y = h2pack(xv.z * s.z, xv.w * s.w);
    *reinterpret_cast<uint2*>(reinterpret_cast<char*>(g_A) + base * 2) = o;
}

// ============ kernel 2: warp-specialized split-K fp16 HMMA GEMM ============
__global__ __launch_bounds__(NTHREADS, 1) void trellis_mma_kernel(
    const int*   __restrict__ packed,
    const float* __restrict__ grid,
    const float* __restrict__ scales,
    const float* __restrict__ sv,
    float*       __restrict__ out)
{
    extern __shared__ char smem[];
    const uint32_t sbase = smem_u32(smem);
    uint32_t* tab = reinterpret_cast<uint32_t*>(smem + SM_TAB);

    const int tid = threadIdx.x;
    const int lid = tid & 31;
    const int wid = tid >> 5;
    const int mbase = blockIdx.x * BM;
    const int nbase = blockIdx.y * BN;
    const int kstart = blockIdx.z * KCHUNK;

    const uint32_t mb = sbase + SM_MBAR;  // full[s] at +s*16, empty[s] at +s*16+8

    for (int e = tid; e < 1024; e += NTHREADS) {
        int b = e & 255;
        tab[e] = h2pack(grid[b & 15], grid[(b >> 4) & 15]);
    }
    if (tid == 0) {
        #pragma unroll
        for (int s = 0; s < NSTAGE; s++) {
            // full: 128 explicit producer arrives (cp.async.mbarrier.arrive is
            // count-neutral; it only delays the phase until A copies land).
            MBAR_INIT(mb + s * 16, 128);
            MBAR_INIT(mb + s * 16 + 8, 256);  // empty: 256 consumer threads
        }
    }
    __syncthreads();

    if (wid >= 8) {
        // ====== PRODUCER: 4 warps, 128 threads = (64 n-pairs) x (2 k-halves)
        const int ptid = tid - 256;          // 0..127
        const int np = ptid & 63;            // n-pair
        const int kh = ptid >> 6;            // k-half: 0 -> k[0,32), 1 -> k[32,64)
        const int n0 = 2 * np;
        const int* pcol = packed + (size_t)(kstart + kh * 32) * NPACK + (nbase >> 1) + np;
        const float* scp0 = scales + nbase + n0;
        const float sv0 = sv[nbase + n0], sv1 = sv[nbase + n0 + 1];
        const uint32_t* tabc = tab + ((ptid >> 3) & 3) * 256;

        for (int i = 0; i < NK_LOCAL; i++) {
            const int s = i % NSTAGE;
            const int w = i / NSTAGE;
            const uint32_t fullb  = mb + s * 16;
            const uint32_t emptyb = mb + s * 16 + 8;
            if (w) MBAR_WAIT(emptyb, (uint32_t)((w - 1) & 1));
            const int k0 = i * BK;           // offset within this K chunk

            // ---- A: 2048 chunks / 128 thr = 16 cp.async each ----
            #pragma unroll
            for (int c = 0; c < 16; c++) {
                int q = ptid + c * 128;      // 0..2047
                int row = q >> 3;
                int cc = q & 7;
                cp_async16(sbase + SM_A + s * 32768 +
                               SW128((uint32_t)(row * 128 + cc * 16)),
                           g_A + (size_t)(mbase + row) * K_FIXED + kstart + k0 + cc * 8);
            }
            CP_ASYNC_MBAR_ARRIVE(fullb);

            // ---- B: 32 packed LDG + dequant + 8 STS.128 (this thread's k-half)
            const int g = (kstart + k0) >> 7;
            __half2 t0 = __float2half2_rn(scp0[(size_t)g * N_FIXED]     * sv0);
            __half2 t1 = __float2half2_rn(scp0[(size_t)g * N_FIXED + 1] * sv1);
            const uint32_t hsc0 = *reinterpret_cast<uint32_t*>(&t0);
            const uint32_t hsc1 = *reinterpret_cast<uint32_t*>(&t1);
            const int* prow = pcol + (size_t)k0 * NPACK;
            char* bstage = smem + SM_B + s * 16384;

            #pragma unroll
            for (int sub = 0; sub < 2; sub++) {      // two 16-k chunks
                int pb[16];
                #pragma unroll
                for (int j = 0; j < 16; j++)
                    pb[j] = prow[(size_t)(sub * 16 + j) * NPACK];
                uint32_t o0[8], o1[8];
                #pragma unroll
                for (int j = 0; j < 8; j++) {
                    uint32_t wa = tabc[pb[2 * j] & 255];
                    uint32_t wb = tabc[pb[2 * j + 1] & 255];
                    uint32_t u0 = __byte_perm(wa, wb, 0x5410);
                    uint32_t u1 = __byte_perm(wa, wb, 0x7632);
                    o0[j] = hmul2(u0, hsc0);
                    o1[j] = hmul2(u1, hsc1);
                }
                uint32_t b0 = (uint32_t)(n0 * 128 + kh * 64 + sub * 32);
                uint32_t b1 = (uint32_t)((n0 + 1) * 128 + kh * 64 + sub * 32);
                *reinterpret_cast<uint4*>(bstage + SW128(b0))      = make_uint4(o0[0], o0[1], o0[2], o0[3]);
                *reinterpret_cast<uint4*>(bstage + SW128(b0 + 16)) = make_uint4(o0[4], o0[5], o0[6], o0[7]);
                *reinterpret_cast<uint4*>(bstage + SW128(b1))      = make_uint4(o1[0], o1[1], o1[2], o1[3]);
                *reinterpret_cast<uint4*>(bstage + SW128(b1 + 16)) = make_uint4(o1[4], o1[5], o1[6], o1[7]);
            }
            MBAR_ARRIVE(fullb);
        }
    } else {
        // ================= CONSUMER: 8 warps, 4m x 2n, warp tile 64x64 =====
        const int mw = wid >> 1;
        const int nw = wid & 1;
        const int arow = (lid & 15);
        const int khalf = (lid >> 4) * 16;

        float acc[4][8][4];
        #pragma unroll
        for (int mi = 0; mi < 4; mi++)
            #pragma unroll
            for (int ni = 0; ni < 8; ni++)
                #pragma unroll
                for (int v = 0; v < 4; v++) acc[mi][ni][v] = 0.f;

        for (int i = 0; i < NK_LOCAL; i++) {
            const int s = i % NSTAGE;
            const int w = i / NSTAGE;
            MBAR_WAIT(mb + s * 16, (uint32_t)(w & 1));
            const uint32_t abase = sbase + SM_A + s * 32768;
            const uint32_t bbase = sbase + SM_B + s * 16384;

            #pragma unroll
            for (int kk = 0; kk < 4; kk++) {
                const uint32_t kb = (uint32_t)(kk * 32 + khalf);
                uint32_t bf[8][2];
                #pragma unroll
                for (int nj = 0; nj < 4; nj++) {
                    uint32_t ro = (uint32_t)((nw * 64 + nj * 16 + arow) * 128);
                    uint32_t r0, r1, r2, r3;
                    ldsm4(r0, r1, r2, r3, bbase + SW128(ro + kb));
                    bf[2 * nj][0] = r0; bf[2 * nj][1] = r2;
                    bf[2 * nj + 1][0] = r1; bf[2 * nj + 1][1] = r3;
                }
                #pragma unroll
                for (int mi = 0; mi < 4; mi++) {
                    uint32_t ah[4];
                    uint32_t ro = (uint32_t)((mw * 64 + mi * 16 + arow) * 128);
                    ldsm4(ah[0], ah[1], ah[2], ah[3], abase + SW128(ro + kb));
                    #pragma unroll
                    for (int ni = 0; ni < 8; ni++)
                        mma16816(acc[mi][ni], ah, bf[ni]);
                }
            }
            MBAR_ARRIVE(mb + s * 16 + 8);
        }

        // ---- epilogue: atomic reduce partials into out ----
        const int er = lid >> 2;
        const int ec = (lid & 3) * 2;
        #pragma unroll
        for (int mi = 0; mi < 4; mi++) {
            #pragma unroll
            for (int ni = 0; ni < 8; ni++) {
                int row = mbase + mw * 64 + mi * 16 + er;
                int col = nbase + nw * 64 + ni * 8 + ec;
                float* p0 = out + (size_t)row * N_FIXED + col;
                float* p1 = out + (size_t)(row + 8) * N_FIXED + col;
                redadd(p0,     acc[mi][ni][0]);
                redadd(p0 + 1, acc[mi][ni][1]);
                redadd(p1,     acc[mi][ni][2]);
                redadd(p1 + 1, acc[mi][ni][3]);
            }
        }
    }
}

// ============ host launcher ============
extern "C" void kernel_launch(void* const* d_in, const int* in_sizes, int n_in,
                              void* d_out, int out_size)
{
    const float* x      = (const float*)d_in[0];
    const int*   packed = (const int*)  d_in[1];
    const float* grid   = (const float*)d_in[2];
    const float* scales = (const float*)d_in[3];
    const float* su     = (const float*)d_in[4];
    const float* sv     = (const float*)d_in[5];
    float* out = (float*)d_out;

    cudaFuncSetAttribute(trellis_mma_kernel,
                         cudaFuncAttributeMaxDynamicSharedMemorySize, SMEM_TOTAL);

    // zero-init out for atomic accumulation (graph-capturable memset)
    cudaMemsetAsync(out, 0, (size_t)M_FIXED * N_FIXED * sizeof(float));

    precompute_a<<<(M_FIXED * K_FIXED) / 1024, 256>>>(x, su);

    dim3 grd(M_FIXED / BM, N_FIXED / BN, SPLITK);
    trellis_mma_kernel<<<grd, NTHREADS, SMEM_TOTAL>>>(packed, grid, scales, sv, out);
}

// round 13
// speedup vs baseline: 1.0658x; 1.0221x over previous
#include <cuda_runtime.h>
#include <cuda_fp16.h>
#include <cstdint>

// ============ problem constants ============
#define M_FIXED 512
#define K_FIXED 8192
#define N_FIXED 8192
#define NPACK   (N_FIXED / 2)

#define BM 256
#define BN 128
#define BK 64
#define SPLITK 8
#define KCHUNK (K_FIXED / SPLITK)     // 1024
#define NK_LOCAL (KCHUNK / BK)        // 16
#define KTILES (K_FIXED / BK)         // 128
#define NSTAGE 3
#define NTHREADS 384   // 8 consumer warps (4m x 2n, 64x64) + 4 producer warps

// Precomputed A = x*su in fp16, TILE-BLOCKED PRE-SWIZZLED layout:
// block (mt, kt) = 32KB at offset ((mt*KTILES + kt) << 15); within a block the
// bytes are the exact SW128-swizzled smem image of the 256x64 fp16 tile.
__device__ __half g_A[M_FIXED * (size_t)K_FIXED];

// ============ smem layout (bytes) ============
#define SM_TAB  0                     // half2 LUT, 4 copies x 256 x 4B = 4096
#define SM_MBAR 4096                  // full[3]/empty[3]: 6 x 8B
#define SM_A    8192                  // 3 stages x 32768 B
#define SM_B    (SM_A + NSTAGE * 32768)
#define SMEM_TOTAL (SM_B + NSTAGE * 16384)   // 155648 B

#define SW128(off) ((off) ^ (((off) >> 3) & 0x70))

__device__ __forceinline__ uint32_t smem_u32(const void* p) {
    uint32_t a;
    asm("{ .reg .u64 t; cvta.to.shared.u64 t, %1; cvt.u32.u64 %0, t; }" : "=r"(a) : "l"(p));
    return a;
}
__device__ __forceinline__ void ldsm4(uint32_t& r0, uint32_t& r1, uint32_t& r2,
                                      uint32_t& r3, uint32_t addr) {
    asm volatile("ldmatrix.sync.aligned.m8n8.x4.shared.b16 {%0,%1,%2,%3}, [%4];"
                 : "=r"(r0), "=r"(r1), "=r"(r2), "=r"(r3) : "r"(addr));
}
__device__ __forceinline__ void mma16816(float* d, const uint32_t* a, const uint32_t* b) {
    asm volatile(
        "mma.sync.aligned.m16n8k16.row.col.f32.f16.f16.f32 "
        "{%0,%1,%2,%3}, {%4,%5,%6,%7}, {%8,%9}, {%0,%1,%2,%3};"
        : "+f"(d[0]), "+f"(d[1]), "+f"(d[2]), "+f"(d[3])
        : "r"(a[0]), "r"(a[1]), "r"(a[2]), "r"(a[3]), "r"(b[0]), "r"(b[1]));
}
__device__ __forceinline__ uint32_t h2pack(float lo, float hi) {
    __half2 v = __floats2half2_rn(lo, hi);
    return *reinterpret_cast<uint32_t*>(&v);
}
__device__ __forceinline__ uint32_t hmul2(uint32_t a, uint32_t b) {
    uint32_t r;
    asm("mul.f16x2 %0, %1, %2;" : "=r"(r) : "r"(a), "r"(b));
    return r;
}
__device__ __forceinline__ void redadd(float* p, float v) {
    asm volatile("red.global.add.f32 [%0], %1;" :: "l"(p), "f"(v) : "memory");
}
__device__ __forceinline__ void bulk_copy_g2s(uint32_t dst, const void* src,
                                              uint32_t bytes, uint32_t mbar) {
    asm volatile(
        "cp.async.bulk.shared::cluster.global.mbarrier::complete_tx::bytes "
        "[%0], [%1], %2, [%3];"
        :: "r"(dst), "l"(src), "r"(bytes), "r"(mbar) : "memory");
}

#define MBAR_INIT(addr, cnt) \
    asm volatile("mbarrier.init.shared.b64 [%0], %1;" :: "r"(addr), "r"(cnt) : "memory")
#define MBAR_ARRIVE(addr) \
    asm volatile("mbarrier.arrive.shared.b64 _, [%0];" :: "r"(addr) : "memory")
#define MBAR_EXPECT_TX(addr, tx) \
    asm volatile("mbarrier.arrive.expect_tx.shared.b64 _, [%0], %1;" \
                 :: "r"(addr), "r"((uint32_t)(tx)) : "memory")
#define MBAR_WAIT(addr, par) do {                                              \
    uint32_t _m = (addr), _p = (par), _d;                                      \
    asm volatile("{ .reg .pred p; mbarrier.try_wait.parity.acquire.cta.shared::cta.b64 p, [%1], %2;" \
                 " selp.b32 %0, 1, 0, p; }" : "=r"(_d) : "r"(_m), "r"(_p) : "memory"); \
    if (!_d) {                                                                 \
        asm volatile("{ .reg .pred P1; WL_%=:"                                 \
            " mbarrier.try_wait.parity.acquire.cta.shared::cta.b64 P1, [%0], %1, 0x989680;" \
            " @P1 bra.uni WD_%=; bra.uni WL_%=; WD_%=: }"                      \
            :: "r"(_m), "r"(_p) : "memory");                                   \
    } } while (0)

// ============ kernel 1: A = x * su -> fp16, tile-blocked + swizzled ============
__global__ __launch_bounds__(256) void precompute_a(const float* __restrict__ x,
                                                    const float* __restrict__ su) {
    int chunk = blockIdx.x * 256 + threadIdx.x;   // one 16B chunk (8 halves)
    int m = chunk >> 10;                          // K/8 = 1024 chunks per row
    int k = (chunk & 1023) * 8;
    const float4* xp = reinterpret_cast<const float4*>(x + (size_t)m * K_FIXED + k);
    const float4* sp = reinterpret_cast<const float4*>(su + k);
    float4 x0 = xp[0], x1 = xp[1];
    float4 s0 = sp[0], s1 = sp[1];
    uint4 v;
    v.x = h2pack(x0.x * s0.x, x0.y * s0.y);
    v.y = h2pack(x0.z * s0.z, x0.w * s0.w);
    v.z = h2pack(x1.x * s1.x, x1.y * s1.y);
    v.w = h2pack(x1.z * s1.z, x1.w * s1.w);
    int mt = m >> 8;                 // m-tile (BM=256)
    int r  = m & 255;                // row within tile
    int kt = k >> 6;                 // k-tile (BK=64)
    int c16 = (k >> 3) & 7;          // 16B chunk within row
    size_t off = ((size_t)(mt * KTILES + kt) << 15) +
                 SW128((uint32_t)(r * 128 + c16 * 16));
    *reinterpret_cast<uint4*>(reinterpret_cast<char*>(g_A) + off) = v;
}

// ============ kernel 2: warp-specialized split-K fp16 HMMA GEMM ============
__global__ __launch_bounds__(NTHREADS, 1) void trellis_mma_kernel(
    const int*   __restrict__ packed,
    const float* __restrict__ grid,
    const float* __restrict__ scales,
    const float* __restrict__ sv,
    float*       __restrict__ out)
{
    extern __shared__ char smem[];
    const uint32_t sbase = smem_u32(smem);
    uint32_t* tab = reinterpret_cast<uint32_t*>(smem + SM_TAB);

    const int tid = threadIdx.x;
    const int lid = tid & 31;
    const int wid = tid >> 5;
    const int mt = blockIdx.x;            // m-tile index
    const int mbase = mt * BM;
    const int nbase = blockIdx.y * BN;
    const int kstart = blockIdx.z * KCHUNK;

    const uint32_t mb = sbase + SM_MBAR;  // full[s] at +s*16, empty[s] at +s*16+8

    for (int e = tid; e < 1024; e += NTHREADS) {
        int b = e & 255;
        tab[e] = h2pack(grid[b & 15], grid[(b >> 4) & 15]);
    }
    if (tid == 0) {
        #pragma unroll
        for (int s = 0; s < NSTAGE; s++) {
            // full: 128 explicit B arrives + 1 expect_tx arrive (ptid 0);
            // the A bulk copy completes via tx bytes.
            MBAR_INIT(mb + s * 16, 129);
            MBAR_INIT(mb + s * 16 + 8, 256);  // empty: 256 consumer threads
        }
    }
    __syncthreads();

    if (wid >= 8) {
        // ====== PRODUCER: 4 warps, 128 threads = (64 n-pairs) x (2 k-halves)
        const int ptid = tid - 256;          // 0..127
        const int np = ptid & 63;            // n-pair
        const int kh = ptid >> 6;            // k-half: 0 -> k[0,32), 1 -> k[32,64)
        const int n0 = 2 * np;
        const int* pcol = packed + (size_t)(kstart + kh * 32) * NPACK + (nbase >> 1) + np;
        const float* scp0 = scales + nbase + n0;
        const float sv0 = sv[nbase + n0], sv1 = sv[nbase + n0 + 1];
        const uint32_t* tabc = tab + ((ptid >> 3) & 3) * 256;
        const char* gA = reinterpret_cast<const char*>(g_A);

        for (int i = 0; i < NK_LOCAL; i++) {
            const int s = i % NSTAGE;
            const int w = i / NSTAGE;
            const uint32_t fullb  = mb + s * 16;
            const uint32_t emptyb = mb + s * 16 + 8;
            if (w) MBAR_WAIT(emptyb, (uint32_t)((w - 1) & 1));
            const int k0 = i * BK;           // offset within this K chunk

            // ---- A: ONE bulk copy of the pre-swizzled 32KB tile ----
            if (ptid == 0) {
                MBAR_EXPECT_TX(fullb, 32768);
                const int kt = (kstart + k0) >> 6;
                bulk_copy_g2s(sbase + SM_A + s * 32768,
                              gA + ((size_t)(mt * KTILES + kt) << 15),
                              32768, fullb);
            }

            // ---- B: 32 packed LDG + dequant + 8 STS.128 (this thread's k-half)
            const int g = (kstart + k0) >> 7;
            __half2 t0 = __float2half2_rn(scp0[(size_t)g * N_FIXED]     * sv0);
            __half2 t1 = __float2half2_rn(scp0[(size_t)g * N_FIXED + 1] * sv1);
            const uint32_t hsc0 = *reinterpret_cast<uint32_t*>(&t0);
            const uint32_t hsc1 = *reinterpret_cast<uint32_t*>(&t1);
            const int* prow = pcol + (size_t)k0 * NPACK;
            char* bstage = smem + SM_B + s * 16384;

            #pragma unroll
            for (int sub = 0; sub < 2; sub++) {      // two 16-k chunks
                int pb[16];
                #pragma unroll
                for (int j = 0; j < 16; j++)
                    pb[j] = prow[(size_t)(sub * 16 + j) * NPACK];
                uint32_t o0[8], o1[8];
                #pragma unroll
                for (int j = 0; j < 8; j++) {
                    uint32_t wa = tabc[pb[2 * j] & 255];
                    uint32_t wb = tabc[pb[2 * j + 1] & 255];
                    uint32_t u0 = __byte_perm(wa, wb, 0x5410);
                    uint32_t u1 = __byte_perm(wa, wb, 0x7632);
                    o0[j] = hmul2(u0, hsc0);
                    o1[j] = hmul2(u1, hsc1);
                }
                uint32_t b0 = (uint32_t)(n0 * 128 + kh * 64 + sub * 32);
                uint32_t b1 = (uint32_t)((n0 + 1) * 128 + kh * 64 + sub * 32);
                *reinterpret_cast<uint4*>(bstage + SW128(b0))      = make_uint4(o0[0], o0[1], o0[2], o0[3]);
                *reinterpret_cast<uint4*>(bstage + SW128(b0 + 16)) = make_uint4(o0[4], o0[5], o0[6], o0[7]);
                *reinterpret_cast<uint4*>(bstage + SW128(b1))      = make_uint4(o1[0], o1[1], o1[2], o1[3]);
                *reinterpret_cast<uint4*>(bstage + SW128(b1 + 16)) = make_uint4(o1[4], o1[5], o1[6], o1[7]);
            }
            MBAR_ARRIVE(fullb);
        }
    } else {
        // ================= CONSUMER: 8 warps, 4m x 2n, warp tile 64x64 =====
        const int mw = wid >> 1;
        const int nw = wid & 1;
        const int arow = (lid & 15);
        const int khalf = (lid >> 4) * 16;

        float acc[4][8][4];
        #pragma unroll
        for (int mi = 0; mi < 4; mi++)
            #pragma unroll
            for (int ni = 0; ni < 8; ni++)
                #pragma unroll
                for (int v = 0; v < 4; v++) acc[mi][ni][v] = 0.f;

        for (int i = 0; i < NK_LOCAL; i++) {
            const int s = i % NSTAGE;
            const int w = i / NSTAGE;
            MBAR_WAIT(mb + s * 16, (uint32_t)(w & 1));
            const uint32_t abase = sbase + SM_A + s * 32768;
            const uint32_t bbase = sbase + SM_B + s * 16384;

            #pragma unroll
            for (int kk = 0; kk < 4; kk++) {
                const uint32_t kb = (uint32_t)(kk * 32 + khalf);
                uint32_t bf[8][2];
                #pragma unroll
                for (int nj = 0; nj < 4; nj++) {
                    uint32_t ro = (uint32_t)((nw * 64 + nj * 16 + arow) * 128);
                    uint32_t r0, r1, r2, r3;
                    ldsm4(r0, r1, r2, r3, bbase + SW128(ro + kb));
                    bf[2 * nj][0] = r0; bf[2 * nj][1] = r2;
                    bf[2 * nj + 1][0] = r1; bf[2 * nj + 1][1] = r3;
                }
                #pragma unroll
                for (int mi = 0; mi < 4; mi++) {
                    uint32_t ah[4];
                    uint32_t ro = (uint32_t)((mw * 64 + mi * 16 + arow) * 128);
                    ldsm4(ah[0], ah[1], ah[2], ah[3], abase + SW128(ro + kb));
                    #pragma unroll
                    for (int ni = 0; ni < 8; ni++)
                        mma16816(acc[mi][ni], ah, bf[ni]);
                }
            }
            MBAR_ARRIVE(mb + s * 16 + 8);
        }

        // ---- epilogue: atomic reduce partials into out ----
        const int er = lid >> 2;
        const int ec = (lid & 3) * 2;
        #pragma unroll
        for (int mi = 0; mi < 4; mi++) {
            #pragma unroll
            for (int ni = 0; ni < 8; ni++) {
                int row = mbase + mw * 64 + mi * 16 + er;
                int col = nbase + nw * 64 + ni * 8 + ec;
                float* p0 = out + (size_t)row * N_FIXED + col;
                float* p1 = out + (size_t)(row + 8) * N_FIXED + col;
                redadd(p0,     acc[mi][ni][0]);
                redadd(p0 + 1, acc[mi][ni][1]);
                redadd(p1,     acc[mi][ni][2]);
                redadd(p1 + 1, acc[mi][ni][3]);
            }
        }
    }
}

// ============ host launcher ============
extern "C" void kernel_launch(void* const* d_in, const int* in_sizes, int n_in,
                              void* d_out, int out_size)
{
    const float* x      = (const float*)d_in[0];
    const int*   packed = (const int*)  d_in[1];
    const float* grid   = (const float*)d_in[2];
    const float* scales = (const float*)d_in[3];
    const float* su     = (const float*)d_in[4];
    const float* sv     = (const float*)d_in[5];
    float* out = (float*)d_out;

    cudaFuncSetAttribute(trellis_mma_kernel,
                         cudaFuncAttributeMaxDynamicSharedMemorySize, SMEM_TOTAL);

    // zero-init out for atomic accumulation (graph-capturable memset)
    cudaMemsetAsync(out, 0, (size_t)M_FIXED * N_FIXED * sizeof(float));

    precompute_a<<<(M_FIXED * K_FIXED / 8) / 256, 256>>>(x, su);

    dim3 grd(M_FIXED / BM, N_FIXED / BN, SPLITK);
    trellis_mma_kernel<<<grd, NTHREADS, SMEM_TOTAL>>>(packed, grid, scales, sv, out);
}

// round 14
// speedup vs baseline: 1.0729x; 1.0066x over previous
#include <cuda_runtime.h>
#include <cuda_fp16.h>
#include <cstdint>

// ============ problem constants ============
#define M_FIXED 512
#define K_FIXED 8192
#define N_FIXED 8192
#define NPACK   (N_FIXED / 2)

#define BM 256
#define BN 64
#define BK 64
#define SPLITK 8
#define KCHUNK (K_FIXED / SPLITK)     // 1024
#define NK_LOCAL (KCHUNK / BK)        // 16
#define KTILES (K_FIXED / BK)         // 128
#define NSTAGE 2
#define NTHREADS 192   // 4 consumer warps (4m x 1n, 64x64) + 2 producer warps

// Precomputed A = x*su in fp16, TILE-BLOCKED PRE-SWIZZLED layout:
// block (mt, kt) = 32KB at offset ((mt*KTILES + kt) << 15); within a block the
// bytes are the exact SW128-swizzled smem image of the 256x64 fp16 tile.
__device__ __half g_A[M_FIXED * (size_t)K_FIXED];

// ============ smem layout (bytes) ============
#define SM_TAB  0                     // half2 LUT, 4 copies x 256 x 4B = 4096
#define SM_MBAR 4096                  // full[2]/empty[2]
#define SM_A    8192                  // 2 stages x 32768 B
#define SM_B    (SM_A + NSTAGE * 32768)
#define SMEM_TOTAL (SM_B + NSTAGE * 8192)    // 90112 B -> 2 CTAs/SM

#define SW128(off) ((off) ^ (((off) >> 3) & 0x70))

__device__ __forceinline__ uint32_t smem_u32(const void* p) {
    uint32_t a;
    asm("{ .reg .u64 t; cvta.to.shared.u64 t, %1; cvt.u32.u64 %0, t; }" : "=r"(a) : "l"(p));
    return a;
}
__device__ __forceinline__ void ldsm4(uint32_t& r0, uint32_t& r1, uint32_t& r2,
                                      uint32_t& r3, uint32_t addr) {
    asm volatile("ldmatrix.sync.aligned.m8n8.x4.shared.b16 {%0,%1,%2,%3}, [%4];"
                 : "=r"(r0), "=r"(r1), "=r"(r2), "=r"(r3) : "r"(addr));
}
__device__ __forceinline__ void mma16816(float* d, const uint32_t* a, const uint32_t* b) {
    asm volatile(
        "mma.sync.aligned.m16n8k16.row.col.f32.f16.f16.f32 "
        "{%0,%1,%2,%3}, {%4,%5,%6,%7}, {%8,%9}, {%0,%1,%2,%3};"
        : "+f"(d[0]), "+f"(d[1]), "+f"(d[2]), "+f"(d[3])
        : "r"(a[0]), "r"(a[1]), "r"(a[2]), "r"(a[3]), "r"(b[0]), "r"(b[1]));
}
__device__ __forceinline__ uint32_t h2pack(float lo, float hi) {
    __half2 v = __floats2half2_rn(lo, hi);
    return *reinterpret_cast<uint32_t*>(&v);
}
__device__ __forceinline__ uint32_t hmul2(uint32_t a, uint32_t b) {
    uint32_t r;
    asm("mul.f16x2 %0, %1, %2;" : "=r"(r) : "r"(a), "r"(b));
    return r;
}
__device__ __forceinline__ void redadd(float* p, float v) {
    asm volatile("red.global.add.f32 [%0], %1;" :: "l"(p), "f"(v) : "memory");
}
__device__ __forceinline__ void bulk_copy_g2s(uint32_t dst, const void* src,
                                              uint32_t bytes, uint32_t mbar) {
    asm volatile(
        "cp.async.bulk.shared::cluster.global.mbarrier::complete_tx::bytes "
        "[%0], [%1], %2, [%3];"
        :: "r"(dst), "l"(src), "r"(bytes), "r"(mbar) : "memory");
}

#define MBAR_INIT(addr, cnt) \
    asm volatile("mbarrier.init.shared.b64 [%0], %1;" :: "r"(addr), "r"(cnt) : "memory")
#define MBAR_ARRIVE(addr) \
    asm volatile("mbarrier.arrive.shared.b64 _, [%0];" :: "r"(addr) : "memory")
#define MBAR_EXPECT_TX(addr, tx) \
    asm volatile("mbarrier.arrive.expect_tx.shared.b64 _, [%0], %1;" \
                 :: "r"(addr), "r"((uint32_t)(tx)) : "memory")
#define MBAR_WAIT(addr, par) do {                                              \
    uint32_t _m = (addr), _p = (par), _d;                                      \
    asm volatile("{ .reg .pred p; mbarrier.try_wait.parity.acquire.cta.shared::cta.b64 p, [%1], %2;" \
                 " selp.b32 %0, 1, 0, p; }" : "=r"(_d) : "r"(_m), "r"(_p) : "memory"); \
    if (!_d) {                                                                 \
        asm volatile("{ .reg .pred P1; WL_%=:"                                 \
            " mbarrier.try_wait.parity.acquire.cta.shared::cta.b64 P1, [%0], %1, 0x989680;" \
            " @P1 bra.uni WD_%=; bra.uni WL_%=; WD_%=: }"                      \
            :: "r"(_m), "r"(_p) : "memory");                                   \
    } } while (0)

// ============ kernel 1: A = x * su -> fp16, tile-blocked + swizzled ============
__global__ __launch_bounds__(256) void precompute_a(const float* __restrict__ x,
                                                    const float* __restrict__ su) {
    int chunk = blockIdx.x * 256 + threadIdx.x;   // one 16B chunk (8 halves)
    int m = chunk >> 10;                          // K/8 = 1024 chunks per row
    int k = (chunk & 1023) * 8;
    const float4* xp = reinterpret_cast<const float4*>(x + (size_t)m * K_FIXED + k);
    const float4* sp = reinterpret_cast<const float4*>(su + k);
    float4 x0 = xp[0], x1 = xp[1];
    float4 s0 = sp[0], s1 = sp[1];
    uint4 v;
    v.x = h2pack(x0.x * s0.x, x0.y * s0.y);
    v.y = h2pack(x0.z * s0.z, x0.w * s0.w);
    v.z = h2pack(x1.x * s1.x, x1.y * s1.y);
    v.w = h2pack(x1.z * s1.z, x1.w * s1.w);
    int mt = m >> 8;                 // m-tile (BM=256)
    int r  = m & 255;                // row within tile
    int kt = k >> 6;                 // k-tile (BK=64)
    int c16 = (k >> 3) & 7;          // 16B chunk within row
    size_t off = ((size_t)(mt * KTILES + kt) << 15) +
                 SW128((uint32_t)(r * 128 + c16 * 16));
    *reinterpret_cast<uint4*>(reinterpret_cast<char*>(g_A) + off) = v;
}

// ============ kernel 2: warp-specialized split-K fp16 HMMA GEMM, 2 CTA/SM ====
__global__ __launch_bounds__(NTHREADS, 2) void trellis_mma_kernel(
    const int*   __restrict__ packed,
    const float* __restrict__ grid,
    const float* __restrict__ scales,
    const float* __restrict__ sv,
    float*       __restrict__ out)
{
    extern __shared__ char smem[];
    const uint32_t sbase = smem_u32(smem);
    uint32_t* tab = reinterpret_cast<uint32_t*>(smem + SM_TAB);

    const int tid = threadIdx.x;
    const int lid = tid & 31;
    const int wid = tid >> 5;
    const int mt = blockIdx.x;            // m-tile index (0..1)
    const int mbase = mt * BM;
    const int nbase = blockIdx.y * BN;
    const int kstart = blockIdx.z * KCHUNK;

    const uint32_t mb = sbase + SM_MBAR;  // full[s] at +s*16, empty[s] at +s*16+8

    for (int e = tid; e < 1024; e += NTHREADS) {
        int b = e & 255;
        tab[e] = h2pack(grid[b & 15], grid[(b >> 4) & 15]);
    }
    if (tid == 0) {
        #pragma unroll
        for (int s = 0; s < NSTAGE; s++) {
            // full: 64 explicit B arrives + 1 expect_tx arrive (ptid 0);
            // the A bulk copy completes via tx bytes.
            MBAR_INIT(mb + s * 16, 65);
            MBAR_INIT(mb + s * 16 + 8, 128);  // empty: 128 consumer threads
        }
    }
    __syncthreads();

    if (wid >= 4) {
        // ====== PRODUCER: 2 warps, 64 threads = (32 n-pairs) x (2 k-halves)
        const int ptid = tid - 128;          // 0..63
        const int np = ptid & 31;            // n-pair (0..31)
        const int kh = ptid >> 5;            // k-half: 0 -> k[0,32), 1 -> k[32,64)
        const int n0 = 2 * np;
        const int* pcol = packed + (size_t)(kstart + kh * 32) * NPACK + (nbase >> 1) + np;
        const float* scp0 = scales + nbase + n0;
        const float sv0 = sv[nbase + n0], sv1 = sv[nbase + n0 + 1];
        const uint32_t* tabc = tab + ((ptid >> 3) & 3) * 256;
        const char* gA = reinterpret_cast<const char*>(g_A);

        for (int i = 0; i < NK_LOCAL; i++) {
            const int s = i % NSTAGE;
            const int w = i / NSTAGE;
            const uint32_t fullb  = mb + s * 16;
            const uint32_t emptyb = mb + s * 16 + 8;
            if (w) MBAR_WAIT(emptyb, (uint32_t)((w - 1) & 1));
            const int k0 = i * BK;           // offset within this K chunk

            // ---- A: ONE bulk copy of the pre-swizzled 32KB tile ----
            if (ptid == 0) {
                MBAR_EXPECT_TX(fullb, 32768);
                const int kt = (kstart + k0) >> 6;
                bulk_copy_g2s(sbase + SM_A + s * 32768,
                              gA + ((size_t)(mt * KTILES + kt) << 15),
                              32768, fullb);
            }

            // ---- B: 32 packed LDG + dequant + 4 STS.128 (this thread's k-half)
            const int g = (kstart + k0) >> 7;
            __half2 t0 = __float2half2_rn(scp0[(size_t)g * N_FIXED]     * sv0);
            __half2 t1 = __float2half2_rn(scp0[(size_t)g * N_FIXED + 1] * sv1);
            const uint32_t hsc0 = *reinterpret_cast<uint32_t*>(&t0);
            const uint32_t hsc1 = *reinterpret_cast<uint32_t*>(&t1);
            const int* prow = pcol + (size_t)k0 * NPACK;
            char* bstage = smem + SM_B + s * 8192;

            #pragma unroll
            for (int sub = 0; sub < 2; sub++) {      // two 16-k chunks
                int pb[16];
                #pragma unroll
                for (int j = 0; j < 16; j++)
                    pb[j] = prow[(size_t)(sub * 16 + j) * NPACK];
                uint32_t o0[8], o1[8];
                #pragma unroll
                for (int j = 0; j < 8; j++) {
                    uint32_t wa = tabc[pb[2 * j] & 255];
                    uint32_t wb = tabc[pb[2 * j + 1] & 255];
                    uint32_t u0 = __byte_perm(wa, wb, 0x5410);
                    uint32_t u1 = __byte_perm(wa, wb, 0x7632);
                    o0[j] = hmul2(u0, hsc0);
                    o1[j] = hmul2(u1, hsc1);
                }
                uint32_t b0 = (uint32_t)(n0 * 128 + kh * 64 + sub * 32);
                uint32_t b1 = (uint32_t)((n0 + 1) * 128 + kh * 64 + sub * 32);
                *reinterpret_cast<uint4*>(bstage + SW128(b0))      = make_uint4(o0[0], o0[1], o0[2], o0[3]);
                *reinterpret_cast<uint4*>(bstage + SW128(b0 + 16)) = make_uint4(o0[4], o0[5], o0[6], o0[7]);
                *reinterpret_cast<uint4*>(bstage + SW128(b1))      = make_uint4(o1[0], o1[1], o1[2], o1[3]);
                *reinterpret_cast<uint4*>(bstage + SW128(b1 + 16)) = make_uint4(o1[4], o1[5], o1[6], o1[7]);
            }
            MBAR_ARRIVE(fullb);
        }
    } else {
        // ================= CONSUMER: 4 warps, 4m x 1n, warp tile 64x64 =====
        const int mw = wid;
        const int arow = (lid & 15);
        const int khalf = (lid >> 4) * 16;

        float acc[4][8][4];
        #pragma unroll
        for (int mi = 0; mi < 4; mi++)
            #pragma unroll
            for (int ni = 0; ni < 8; ni++)
                #pragma unroll
                for (int v = 0; v < 4; v++) acc[mi][ni][v] = 0.f;

        for (int i = 0; i < NK_LOCAL; i++) {
            const int s = i % NSTAGE;
            const int w = i / NSTAGE;
            MBAR_WAIT(mb + s * 16, (uint32_t)(w & 1));
            const uint32_t abase = sbase + SM_A + s * 32768;
            const uint32_t bbase = sbase + SM_B + s * 8192;

            #pragma unroll
            for (int kk = 0; kk < 4; kk++) {
                const uint32_t kb = (uint32_t)(kk * 32 + khalf);
                uint32_t bf[8][2];
                #pragma unroll
                for (int nj = 0; nj < 4; nj++) {
                    uint32_t ro = (uint32_t)((nj * 16 + arow) * 128);
                    uint32_t r0, r1, r2, r3;
                    ldsm4(r0, r1, r2, r3, bbase + SW128(ro + kb));
                    bf[2 * nj][0] = r0; bf[2 * nj][1] = r2;
                    bf[2 * nj + 1][0] = r1; bf[2 * nj + 1][1] = r3;
                }
                #pragma unroll
                for (int mi = 0; mi < 4; mi++) {
                    uint32_t ah[4];
                    uint32_t ro = (uint32_t)((mw * 64 + mi * 16 + arow) * 128);
                    ldsm4(ah[0], ah[1], ah[2], ah[3], abase + SW128(ro + kb));
                    #pragma unroll
                    for (int ni = 0; ni < 8; ni++)
                        mma16816(acc[mi][ni], ah, bf[ni]);
                }
            }
            MBAR_ARRIVE(mb + s * 16 + 8);
        }

        // ---- epilogue: atomic reduce partials into out ----
        const int er = lid >> 2;
        const int ec = (lid & 3) * 2;
        #pragma unroll
        for (int mi = 0; mi < 4; mi++) {
            #pragma unroll
            for (int ni = 0; ni < 8; ni++) {
                int row = mbase + mw * 64 + mi * 16 + er;
                int col = nbase + ni * 8 + ec;
                float* p0 = out + (size_t)row * N_FIXED + col;
                float* p1 = out + (size_t)(row + 8) * N_FIXED + col;
                redadd(p0,     acc[mi][ni][0]);
                redadd(p0 + 1, acc[mi][ni][1]);
                redadd(p1,     acc[mi][ni][2]);
                redadd(p1 + 1, acc[mi][ni][3]);
            }
        }
    }
}

// ============ host launcher ============
extern "C" void kernel_launch(void* const* d_in, const int* in_sizes, int n_in,
                              void* d_out, int out_size)
{
    const float* x      = (const float*)d_in[0];
    const int*   packed = (const int*)  d_in[1];
    const float* grid   = (const float*)d_in[2];
    const float* scales = (const float*)d_in[3];
    const float* su     = (const float*)d_in[4];
    const float* sv     = (const float*)d_in[5];
    float* out = (float*)d_out;

    cudaFuncSetAttribute(trellis_mma_kernel,
                         cudaFuncAttributeMaxDynamicSharedMemorySize, SMEM_TOTAL);

    // zero-init out for atomic accumulation (graph-capturable memset)
    cudaMemsetAsync(out, 0, (size_t)M_FIXED * N_FIXED * sizeof(float));

    precompute_a<<<(M_FIXED * K_FIXED / 8) / 256, 256>>>(x, su);

    dim3 grd(M_FIXED / BM, N_FIXED / BN, SPLITK);
    trellis_mma_kernel<<<grd, NTHREADS, SMEM_TOTAL>>>(packed, grid, scales, sv, out);
}